// round 16
// baseline (speedup 1.0000x reference)
#include <cuda_runtime.h>
#include <cstdint>

// ---- problem constants ----
#define N_OBJ     16
#define DIM_IN    256
#define NCOLS     64
#define BM        256               // rows per block
#define ROWSTRIDE 4096              // floats between batch rows of x
#define OUTSTRIDE 1024              // floats between batch rows of out
#define KC        16                // k per pipeline chunk (64 B per row)
#define NCHUNK    (DIM_IN / KC)     // 16
#define NSTAGE    3

#define ASTAGE_BYTES 16384          // 256 rows x 64 B (XOR-16B swizzled)
#define BSTAGE_BYTES 4096           // 2 k-steps x 2048 B
#define SM_A         0
#define SM_B         (NSTAGE * ASTAGE_BYTES)          // 49152
#define SM_BIAS      (SM_B + NSTAGE * BSTAGE_BYTES)   // 61440
#define SMEM_BYTES   (SM_BIAS + 256)                  // 61696 -> 2 blocks/SM

// Fragment-major tf32 W, per obj 16384 words:
// word = gc*1024 + sl*512 + (j>>2)*256 + ((j>>1)&1)*128 + lane*4 + (j&1)*2 + slot
__device__ uint32_t Wfrag_g[N_OBJ * 16384];

__device__ __forceinline__ uint32_t f2tf32(float f) {
    uint32_t r; asm("cvt.rna.tf32.f32 %0, %1;" : "=r"(r) : "f"(f)); return r;
}
__device__ __forceinline__ void cp16(uint32_t dst, const void* src) {
    asm volatile("cp.async.cg.shared.global [%0], [%1], 16;" :: "r"(dst), "l"(src));
}

// ---- pre-kernel: build fragment-major tf32 W (128 blocks) ----
__global__ void __launch_bounds__(256)
prep_kernel(const float* __restrict__ W)
{
    const int o    = blockIdx.x;
    const int slab = blockIdx.y;          // 0..7
    const int tid  = threadIdx.x;
    uint32_t* Wf = Wfrag_g + o * 16384;
    const float4* Wg4 = (const float4*)(W + (size_t)o * (NCOLS * DIM_IN));
    #pragma unroll
    for (int i = 0; i < 2; ++i) {
        int idx4 = tid + (slab * 2 + i) * 256;
        int m = idx4 * 4;                 // linear float index within object
        float4 v = Wg4[idx4];
        int k  = m & 7;                   // 0 or 4
        int d  = (m >> 3) & 255;
        int n0 = (m >> 12) * 16 + ((m >> 11) & 1) * 8 + k;
        int j  = n0 >> 3;
        int s  = d >> 3;                  // global k-step 0..31
        int c  = d & 7;
        int slot = c >> 2;
        int cl   = c & 3;
        int gcb  = s >> 1;                // chunk 0..15
        int sl   = s & 1;                 // step within chunk
        uint32_t base = gcb * 1024 + sl * 512 + (j >> 2) * 256
                      + ((j >> 1) & 1) * 128 + (j & 1) * 2 + slot;
        float vv[4] = {v.x, v.y, v.z, v.w};
        #pragma unroll
        for (int t = 0; t < 4; ++t) {
            int g = (n0 & 7) + t;         // k=0 -> g 0..3, k=4 -> g 4..7
            Wf[base + (g * 4 + cl) * 4] = f2tf32(vv[t]);
        }
    }
}

__global__ void __launch_bounds__(256, 2)
objdec_kernel(const float* __restrict__ x,
              const float* __restrict__ bias,
              float* __restrict__ out)
{
    extern __shared__ char smem[];
    float* bsm = (float*)(smem + SM_BIAS);

    const int tid   = threadIdx.x;
    const int warp  = tid >> 5;
    const int lane  = tid & 31;
    const int o     = blockIdx.y;
    const int rbase = blockIdx.x * BM;
    const float* xg = x + (size_t)rbase * ROWSTRIDE + o * DIM_IN;

    const uint32_t sbase = (uint32_t)__cvta_generic_to_shared(smem);

    // ---- A cp.async addressing: 4 threads/row (64 B rows), XOR swizzle ----
    const float* asrc[4];
    uint32_t adst[4];
    {
        #pragma unroll
        for (int q = 0; q < 4; ++q) {
            int lin  = tid + q * 256;
            int row  = lin >> 2;          // 0..255
            int quad = lin & 3;           // 16B quad within 64B row
            asrc[q] = xg + (size_t)row * ROWSTRIDE + quad * 4;
            adst[q] = sbase + SM_A + row * 64 + ((quad ^ ((row >> 1) & 3)) << 4);
        }
    }
    // ---- B cp.async addressing: thread t copies 16 B of the 4 KB slab ----
    const uint32_t* bsrc = Wfrag_g + o * 16384 + tid * 4;   // + gc*1024
    const uint32_t  bdst = sbase + SM_B + tid * 16;         // + (gc%3)*4096

    // ---- prologue: chunks 0 and 1 ----
    #pragma unroll
    for (int q = 0; q < 4; ++q) cp16(adst[q], asrc[q]);
    cp16(bdst, bsrc);
    asm volatile("cp.async.commit_group;\n");
    #pragma unroll
    for (int q = 0; q < 4; ++q) cp16(adst[q] + ASTAGE_BYTES, asrc[q] + KC);
    cp16(bdst + BSTAGE_BYTES, bsrc + 1024);
    asm volatile("cp.async.commit_group;\n");

    if (tid < NCOLS) bsm[tid] = bias[o * NCOLS + tid];

    // ---- warp tiling: 4 mwarps x 2 nwarps; warp = 64 rows x 32 cols ----
    const int mw = warp >> 1;
    const int nw = warp & 1;
    const int g  = lane >> 2;
    const int c  = lane & 3;

    float acc[4][4][4];
    #pragma unroll
    for (int mi = 0; mi < 4; ++mi)
        #pragma unroll
        for (int j = 0; j < 4; ++j)
            #pragma unroll
            for (int q = 0; q < 4; ++q) acc[mi][j][q] = 0.0f;

    // ldmatrix lane geometry
    const int m_ = lane >> 3;             // matrix 0..3
    const int rr = lane & 7;
    const int qh = m_ >> 1;               // k-half (quad offset 0/1)
    uint32_t rbyte[4];                    // row byte offset per mi
    uint32_t xr[4];                       // swizzle XOR per mi
    #pragma unroll
    for (int mi = 0; mi < 4; ++mi) {
        int rowidx = mw * 64 + mi * 16 + (m_ & 1) * 8 + rr;
        rbyte[mi] = rowidx * 64;
        xr[mi]    = (rowidx >> 1) & 3;
    }
    // B LDS base (this warp's n-half: jgrp = nw)
    const uint32_t bbase = sbase + SM_B + nw * 1024 + lane * 16;

    for (int gc = 0; gc < NCHUNK; ++gc) {
        if (gc < NCHUNK - 1) {
            asm volatile("cp.async.wait_group 1;\n" ::: "memory");
        } else {
            asm volatile("cp.async.wait_group 0;\n" ::: "memory");
        }
        __syncthreads();
        // refill stage (gc+2)%3 with chunk gc+2
        const int nxt = gc + 2;
        if (nxt < NCHUNK) {
            const uint32_t sa = (nxt % NSTAGE) * ASTAGE_BYTES;
            const uint32_t sb = (nxt % NSTAGE) * BSTAGE_BYTES;
            const int aoff = nxt * KC;
            #pragma unroll
            for (int q = 0; q < 4; ++q) cp16(adst[q] + sa, asrc[q] + aoff);
            cp16(bdst + sb, bsrc + nxt * 1024);
            asm volatile("cp.async.commit_group;\n");
        }

        const uint32_t abA = sbase + SM_A + (gc % NSTAGE) * ASTAGE_BYTES;
        const uint32_t bbB = bbase + (gc % NSTAGE) * BSTAGE_BYTES;

        #pragma unroll
        for (int ks = 0; ks < 2; ++ks) {
            // A fragments: 4 x ldmatrix.x4 from swizzled smem
            uint32_t a[4][4];
            #pragma unroll
            for (int mi = 0; mi < 4; ++mi) {
                const uint32_t addr =
                    abA + rbyte[mi] + ((((uint32_t)(ks * 2) + qh) ^ xr[mi]) << 4);
                asm volatile(
                    "ldmatrix.sync.aligned.m8n8.x4.shared.b16 {%0,%1,%2,%3}, [%4];"
                    : "=r"(a[mi][0]), "=r"(a[mi][1]), "=r"(a[mi][2]), "=r"(a[mi][3])
                    : "r"(addr));
            }

            // B fragments: 2 x LDS.128 (j-pair interleaved, conflict-free)
            uint32_t b[8];
            asm volatile("ld.shared.v4.b32 {%0,%1,%2,%3}, [%4];"
                         : "=r"(b[0]), "=r"(b[1]), "=r"(b[2]), "=r"(b[3])
                         : "r"(bbB + ks * 2048));
            asm volatile("ld.shared.v4.b32 {%0,%1,%2,%3}, [%4];"
                         : "=r"(b[4]), "=r"(b[5]), "=r"(b[6]), "=r"(b[7])
                         : "r"(bbB + ks * 2048 + 512));

            // 16 MMAs
            #pragma unroll
            for (int mi = 0; mi < 4; ++mi) {
                #pragma unroll
                for (int j = 0; j < 4; ++j) {
                    asm volatile(
                        "mma.sync.aligned.m16n8k8.row.col.f32.tf32.tf32.f32 "
                        "{%0,%1,%2,%3}, {%4,%5,%6,%7}, {%8,%9}, {%0,%1,%2,%3};\n"
                        : "+f"(acc[mi][j][0]), "+f"(acc[mi][j][1]),
                          "+f"(acc[mi][j][2]), "+f"(acc[mi][j][3])
                        : "r"(a[mi][0]), "r"(a[mi][1]), "r"(a[mi][2]), "r"(a[mi][3]),
                          "r"(b[(j >> 1) * 4 + (j & 1) * 2]),
                          "r"(b[(j >> 1) * 4 + (j & 1) * 2 + 1]));
                }
            }
        }
    }

    // ---- epilogue: bias + float2 stores ----
    #pragma unroll
    for (int mi = 0; mi < 4; ++mi) {
        const int row0 = rbase + mw * 64 + mi * 16 + g;
        const int row1 = row0 + 8;
        #pragma unroll
        for (int j = 0; j < 4; ++j) {
            const int col = nw * 32 + j * 8 + 2 * c;
            float bv0 = bsm[col];
            float bv1 = bsm[col + 1];
            float2 v0 = make_float2(acc[mi][j][0] + bv0, acc[mi][j][1] + bv1);
            float2 v1 = make_float2(acc[mi][j][2] + bv0, acc[mi][j][3] + bv1);
            *reinterpret_cast<float2*>(
                out + (size_t)row0 * OUTSTRIDE + o * NCOLS + col) = v0;
            *reinterpret_cast<float2*>(
                out + (size_t)row1 * OUTSTRIDE + o * NCOLS + col) = v1;
        }
    }
}

extern "C" void kernel_launch(void* const* d_in, const int* in_sizes, int n_in,
                              void* d_out, int out_size)
{
    (void)in_sizes; (void)n_in; (void)out_size;
    const float* x = (const float*)d_in[0];
    const float* W = (const float*)d_in[1];
    const float* b = (const float*)d_in[2];
    float* out = (float*)d_out;

    cudaFuncSetAttribute(objdec_kernel,
                         cudaFuncAttributeMaxDynamicSharedMemorySize, SMEM_BYTES);

    dim3 pgrid(N_OBJ, 8);
    prep_kernel<<<pgrid, 256>>>(W);
    dim3 grid(16384 / BM, N_OBJ);
    objdec_kernel<<<grid, 256, SMEM_BYTES>>>(x, b, out);
}

// round 17
// speedup vs baseline: 1.1459x; 1.1459x over previous
#include <cuda_runtime.h>
#include <cstdint>

// ---- problem constants ----
#define N_OBJ     16
#define DIM_IN    256
#define NCOLS     64
#define BM        128
#define ROWSTRIDE 4096              // floats between batch rows of x
#define OUTSTRIDE 1024              // floats between batch rows of out
#define KC        32                // k per pipeline chunk
#define NCHUNK    (DIM_IN / KC)     // 8
#define NSTAGE    3

#define ASTAGE_BYTES 16384          // 128 rows x 128 B (XOR-16B swizzled)
#define BSTAGE_BYTES 8192           // 4 k-steps x 2048 B
#define SM_A         0
#define SM_B         (NSTAGE * ASTAGE_BYTES)          // 49152
#define SM_BIAS      (SM_B + NSTAGE * BSTAGE_BYTES)   // 73728
#define SMEM_BYTES   (SM_BIAS + 256)                  // 73984 -> 3 blocks/SM

// Fragment-major tf32 W (R14 layout):
// word (per obj) = ck*2048 + sl*512 + (j>>2)*256 + ((j>>1)&1)*128
//                  + (g*4+cl)*4 + (j&1)*2 + slot
//   where n = j*8+g, d = (ck*4+sl)*8 + cl + 4*slot
__device__ uint32_t Wfrag_g[N_OBJ * 16384];

__device__ __forceinline__ uint32_t f2tf32(float f) {
    uint32_t r; asm("cvt.rna.tf32.f32 %0, %1;" : "=r"(r) : "f"(f)); return r;
}
__device__ __forceinline__ void cp16(uint32_t dst, const void* src) {
    asm volatile("cp.async.cg.shared.global [%0], [%1], 16;" :: "r"(dst), "l"(src));
}

// ---- pre-kernel: coalesced-write fragment permute ----
// thread owns 4 consecutive output words (16 B, STG.128); gathers 4 x 4 B.
__global__ void __launch_bounds__(256)
prep_kernel(const float* __restrict__ W)
{
    const int o   = blockIdx.x;           // 0..15
    const int blk = blockIdx.y;           // 0..15
    const int tid = threadIdx.x;
    const int t   = blk * 256 + tid;      // 0..4095 : owns words 4t..4t+3

    // decode fixed fields of word base w0 = 4t
    const int w0   = t * 4;
    const int ck   = w0 >> 11;                    // /2048
    const int sl   = (w0 >> 9) & 3;               // /512 %4
    const int jg   = (w0 >> 8) & 1;               // j>>2
    const int jh   = (w0 >> 7) & 1;               // (j>>1)&1
    const int gl   = (w0 >> 2) & 31;              // g*4+cl
    const int g    = gl >> 2;
    const int cl   = gl & 3;
    const int s    = ck * 4 + sl;                 // global k-step

    const float* Wg = W + (size_t)o * (NCOLS * DIM_IN);
    uint32_t v[4];
    #pragma unroll
    for (int u = 0; u < 4; ++u) {                 // u = jl*2 + slot
        const int jl   = u >> 1;
        const int slot = u & 1;
        const int j    = jg * 4 + jh * 2 + jl;
        const int n    = j * 8 + g;
        const int d    = s * 8 + cl + 4 * slot;
        const int a    = n >> 4;
        const int p    = (n >> 3) & 1;
        const int k    = n & 7;
        // gmem index m = ((a*2+p)*256 + d)*8 + k
        v[u] = f2tf32(Wg[((a * 2 + p) * 256 + d) * 8 + k]);
    }
    *reinterpret_cast<uint4*>(Wfrag_g + o * 16384 + w0) =
        make_uint4(v[0], v[1], v[2], v[3]);
}

__global__ void __launch_bounds__(256, 3)
objdec_kernel(const float* __restrict__ x,
              const float* __restrict__ bias,
              float* __restrict__ out)
{
    extern __shared__ char smem[];
    float* bsm = (float*)(smem + SM_BIAS);

    const int tid   = threadIdx.x;
    const int warp  = tid >> 5;
    const int lane  = tid & 31;
    const int o     = blockIdx.y;
    const int rbase = blockIdx.x * BM;
    const float* xg = x + (size_t)rbase * ROWSTRIDE + o * DIM_IN;

    const uint32_t sbase = (uint32_t)__cvta_generic_to_shared(smem);

    // ---- A cp.async addressing: 8 threads/row; XOR-16B swizzled dst ----
    const float* asrc[4];
    uint32_t adst[4];
    {
        #pragma unroll
        for (int q = 0; q < 4; ++q) {
            int lin  = tid + q * 256;
            int row  = lin >> 3;
            int quad = lin & 7;
            asrc[q] = xg + (size_t)row * ROWSTRIDE + quad * 4;
            adst[q] = sbase + SM_A + row * 128 + ((quad ^ (row & 7)) << 4);
        }
    }
    // ---- B cp.async addressing: thread t copies 32 B of the 8 KB slab ----
    const uint32_t* bsrc = Wfrag_g + o * 16384 + tid * 8;   // + ck*2048
    const uint32_t  bdst = sbase + SM_B + tid * 32;         // + (ck%3)*8192

    // ---- prologue: chunks 0 and 1 (B first: L2-resident, completes early) ----
    cp16(bdst, bsrc);  cp16(bdst + 16, bsrc + 4);
    #pragma unroll
    for (int q = 0; q < 4; ++q) cp16(adst[q], asrc[q]);
    asm volatile("cp.async.commit_group;\n");
    cp16(bdst + BSTAGE_BYTES, bsrc + 2048);
    cp16(bdst + BSTAGE_BYTES + 16, bsrc + 2052);
    #pragma unroll
    for (int q = 0; q < 4; ++q) cp16(adst[q] + ASTAGE_BYTES, asrc[q] + KC);
    asm volatile("cp.async.commit_group;\n");

    if (tid < NCOLS) bsm[tid] = bias[o * NCOLS + tid];

    // ---- warp tiling: 4 mwarps x 2 nwarps; warp = 32 rows x 32 cols ----
    const int mw = warp & 3;
    const int nw = warp >> 2;
    const int g  = lane >> 2;
    const int c  = lane & 3;

    float acc[2][4][4];
    #pragma unroll
    for (int mi = 0; mi < 2; ++mi)
        #pragma unroll
        for (int j = 0; j < 4; ++j)
            #pragma unroll
            for (int q = 0; q < 4; ++q) acc[mi][j][q] = 0.0f;

    // ldmatrix lane geometry
    const int m_   = lane >> 3;
    const int rr   = lane & 7;
    const int qh   = m_ >> 1;
    const uint32_t arow0 = (mw * 32 + (m_ & 1) * 8 + rr) * 128;
    // B LDS base (this warp's n-half), j-pair interleaved
    const uint32_t bbase = sbase + SM_B + nw * 1024 + lane * 16;

    for (int ck = 0; ck < NCHUNK; ++ck) {
        if (ck < NCHUNK - 1) {
            asm volatile("cp.async.wait_group 1;\n" ::: "memory");
        } else {
            asm volatile("cp.async.wait_group 0;\n" ::: "memory");
        }
        __syncthreads();
        // refill stage (ck+2)%3 with chunk ck+2 (B first)
        const int nxt = ck + 2;
        if (nxt < NCHUNK) {
            const uint32_t sa = (nxt % NSTAGE) * ASTAGE_BYTES;
            const uint32_t sb = (nxt % NSTAGE) * BSTAGE_BYTES;
            cp16(bdst + sb, bsrc + nxt * 2048);
            cp16(bdst + sb + 16, bsrc + nxt * 2048 + 4);
            #pragma unroll
            for (int q = 0; q < 4; ++q) cp16(adst[q] + sa, asrc[q] + nxt * KC);
            asm volatile("cp.async.commit_group;\n");
        }

        const uint32_t abA = sbase + SM_A + (ck % NSTAGE) * ASTAGE_BYTES + arow0;
        const uint32_t bbB = bbase + (ck % NSTAGE) * BSTAGE_BYTES;

        #pragma unroll
        for (int ks = 0; ks < 4; ++ks) {
            // A fragments: 2 x ldmatrix.x4 from swizzled smem
            const uint32_t qoff = ((2 * ks + qh) ^ rr) << 4;
            uint32_t a0[4], a1[4];
            asm volatile(
                "ldmatrix.sync.aligned.m8n8.x4.shared.b16 {%0,%1,%2,%3}, [%4];"
                : "=r"(a0[0]), "=r"(a0[1]), "=r"(a0[2]), "=r"(a0[3])
                : "r"(abA + qoff));
            asm volatile(
                "ldmatrix.sync.aligned.m8n8.x4.shared.b16 {%0,%1,%2,%3}, [%4];"
                : "=r"(a1[0]), "=r"(a1[1]), "=r"(a1[2]), "=r"(a1[3])
                : "r"(abA + 16 * 128 + qoff));

            // B fragments: 2 x LDS.128 (j-pair interleaved, conflict-free)
            uint32_t b[8];
            asm volatile("ld.shared.v4.b32 {%0,%1,%2,%3}, [%4];"
                         : "=r"(b[0]), "=r"(b[1]), "=r"(b[2]), "=r"(b[3])
                         : "r"(bbB + ks * 2048));
            asm volatile("ld.shared.v4.b32 {%0,%1,%2,%3}, [%4];"
                         : "=r"(b[4]), "=r"(b[5]), "=r"(b[6]), "=r"(b[7])
                         : "r"(bbB + ks * 2048 + 512));

            // 8 MMAs
            #pragma unroll
            for (int j = 0; j < 4; ++j) {
                asm volatile(
                    "mma.sync.aligned.m16n8k8.row.col.f32.tf32.tf32.f32 "
                    "{%0,%1,%2,%3}, {%4,%5,%6,%7}, {%8,%9}, {%0,%1,%2,%3};\n"
                    : "+f"(acc[0][j][0]), "+f"(acc[0][j][1]),
                      "+f"(acc[0][j][2]), "+f"(acc[0][j][3])
                    : "r"(a0[0]), "r"(a0[1]), "r"(a0[2]), "r"(a0[3]),
                      "r"(b[j * 2]), "r"(b[j * 2 + 1]));
                asm volatile(
                    "mma.sync.aligned.m16n8k8.row.col.f32.tf32.tf32.f32 "
                    "{%0,%1,%2,%3}, {%4,%5,%6,%7}, {%8,%9}, {%0,%1,%2,%3};\n"
                    : "+f"(acc[1][j][0]), "+f"(acc[1][j][1]),
                      "+f"(acc[1][j][2]), "+f"(acc[1][j][3])
                    : "r"(a1[0]), "r"(a1[1]), "r"(a1[2]), "r"(a1[3]),
                      "r"(b[j * 2]), "r"(b[j * 2 + 1]));
            }
        }
    }

    // ---- epilogue: bias + float2 stores ----
    #pragma unroll
    for (int mi = 0; mi < 2; ++mi) {
        const int row0 = rbase + mw * 32 + mi * 16 + g;
        const int row1 = row0 + 8;
        #pragma unroll
        for (int j = 0; j < 4; ++j) {
            const int col = nw * 32 + j * 8 + 2 * c;
            float bv0 = bsm[col];
            float bv1 = bsm[col + 1];
            float2 v0 = make_float2(acc[mi][j][0] + bv0, acc[mi][j][1] + bv1);
            float2 v1 = make_float2(acc[mi][j][2] + bv0, acc[mi][j][3] + bv1);
            *reinterpret_cast<float2*>(
                out + (size_t)row0 * OUTSTRIDE + o * NCOLS + col) = v0;
            *reinterpret_cast<float2*>(
                out + (size_t)row1 * OUTSTRIDE + o * NCOLS + col) = v1;
        }
    }
}

extern "C" void kernel_launch(void* const* d_in, const int* in_sizes, int n_in,
                              void* d_out, int out_size)
{
    (void)in_sizes; (void)n_in; (void)out_size;
    const float* x = (const float*)d_in[0];
    const float* W = (const float*)d_in[1];
    const float* b = (const float*)d_in[2];
    float* out = (float*)d_out;

    cudaFuncSetAttribute(objdec_kernel,
                         cudaFuncAttributeMaxDynamicSharedMemorySize, SMEM_BYTES);

    dim3 pgrid(N_OBJ, 16);
    prep_kernel<<<pgrid, 256>>>(W);
    dim3 grid(16384 / BM, N_OBJ);
    objdec_kernel<<<grid, 256, SMEM_BYTES>>>(x, b, out);
}